// round 1
// baseline (speedup 1.0000x reference)
#include <cuda_runtime.h>
#include <math.h>

// Problem constants (shapes fixed by the dataset)
#define DD 1024
#define SS 2048
#define BBATCH 2
#define NEGV (-1e10f)

// Scratch (device globals — no allocation allowed)
__device__ float g_q[BBATCH * SS * DD];        // 16 MB
__device__ float g_scores[BBATCH * SS * SS];   // 32 MB
__device__ float g_head[BBATCH * SS * DD];     // 16 MB
__device__ float g_h[BBATCH * SS * DD];        // 16 MB
__device__ float g_t[BBATCH * SS * DD];        // 16 MB
__device__ float g_w2[DD * DD];                // 4 MB

// ---------------------------------------------------------------------------
// W2[i,j] = sum_h out_kernel[h*D + i, j]   (out_kernel: [H*D, D] row-major)
// ---------------------------------------------------------------------------
__global__ void w2_reduce_kernel(const float* __restrict__ ok,
                                 float* __restrict__ w2, int H) {
    int idx = blockIdx.x * blockDim.x + threadIdx.x;
    if (idx >= DD * DD) return;
    int i = idx / DD, j = idx % DD;
    float s = 0.f;
    for (int h = 0; h < H; h++)
        s += ok[(size_t)(h * DD + i) * DD + j];
    w2[idx] = s;
}

// ---------------------------------------------------------------------------
// SGEMM NN: C[z] = A[z] @ B[z] (+ epilogue). 128x128 tile, BK=8, 8x8/thread.
// All dims are multiples of 128 (M) / 128 (N) / 8 (K) -> no bounds checks.
// EPI: 0=none, 1=C+=E (same layout as C, causal K-limit on), 2=C+=bias[col],
//      3=swish(C)
// ---------------------------------------------------------------------------
template <int EPI>
__global__ __launch_bounds__(256) void sgemm_nn(
    int M, int N, int K,
    const float* __restrict__ A, const float* __restrict__ B,
    float* __restrict__ C, const float* __restrict__ E,
    long sA, long sB, long sC) {
    const int BM = 128, BN = 128, BK = 8, TM = 8, TN = 8;
    __shared__ float As[BK][BM];
    __shared__ float Bs[BK][BN];

    A += (size_t)blockIdx.z * sA;
    B += (size_t)blockIdx.z * sB;
    C += (size_t)blockIdx.z * sC;
    const float* Eb = (EPI == 1 && E) ? E + (size_t)blockIdx.z * sC : E;

    int rowStart = blockIdx.y * BM;
    int colStart = blockIdx.x * BN;
    int tid = threadIdx.x;

    int loadRowA = tid >> 1;          // 0..127
    int loadColA = (tid & 1) * 4;     // 0 or 4
    int loadRowB = tid >> 5;          // 0..7
    int loadColB = (tid & 31) * 4;    // 0..124
    int tr = (tid >> 4) * TM;
    int tc = (tid & 15) * TN;

    int Keff = K;
    if (EPI == 1) {  // P @ V: P[i,j]==0 for j>i exactly -> clamp K
        Keff = rowStart + BM;
        if (Keff > K) Keff = K;
    }

    float acc[TM][TN];
#pragma unroll
    for (int i = 0; i < TM; i++)
#pragma unroll
        for (int j = 0; j < TN; j++) acc[i][j] = 0.f;

    float rm[TM], rn[TN];
    for (int k0 = 0; k0 < Keff; k0 += BK) {
        float4 a = *(const float4*)(A + (size_t)(rowStart + loadRowA) * K + k0 + loadColA);
        As[loadColA + 0][loadRowA] = a.x;
        As[loadColA + 1][loadRowA] = a.y;
        As[loadColA + 2][loadRowA] = a.z;
        As[loadColA + 3][loadRowA] = a.w;
        *(float4*)(&Bs[loadRowB][loadColB]) =
            *(const float4*)(B + (size_t)(k0 + loadRowB) * N + colStart + loadColB);
        __syncthreads();
#pragma unroll
        for (int k = 0; k < BK; k++) {
#pragma unroll
            for (int i = 0; i < TM; i++) rm[i] = As[k][tr + i];
#pragma unroll
            for (int j = 0; j < TN; j++) rn[j] = Bs[k][tc + j];
#pragma unroll
            for (int i = 0; i < TM; i++)
#pragma unroll
                for (int j = 0; j < TN; j++) acc[i][j] += rm[i] * rn[j];
        }
        __syncthreads();
    }

#pragma unroll
    for (int i = 0; i < TM; i++) {
        int r = rowStart + tr + i;
#pragma unroll
        for (int j = 0; j < TN; j += 4) {
            float4 v;
            float* vp = &v.x;
#pragma unroll
            for (int q = 0; q < 4; q++) {
                float x = acc[i][j + q];
                int c = colStart + tc + j + q;
                if (EPI == 1) x += Eb[(size_t)r * N + c];
                if (EPI == 2) x += E[c];
                if (EPI == 3) x = x / (1.f + expf(-x));
                vp[q] = x;
            }
            *(float4*)(C + (size_t)r * N + colStart + tc + j) = v;
        }
    }
}

// ---------------------------------------------------------------------------
// SGEMM NT for attention scores: C = (A @ B^T) * scale, causal mask -> NEGV.
// A: [M,K], B: [N,K] (both row-major; here both are q_b). Fully-masked tiles
// skip the K loop entirely.
// ---------------------------------------------------------------------------
__global__ __launch_bounds__(256) void sgemm_nt_scores(
    int M, int N, int K,
    const float* __restrict__ A, const float* __restrict__ B,
    float* __restrict__ C, float scale,
    long sA, long sB, long sC) {
    const int BM = 128, BN = 128, BK = 8, TM = 8, TN = 8;
    __shared__ float As[BK][BM];
    __shared__ float Bs[BK][BN];

    A += (size_t)blockIdx.z * sA;
    B += (size_t)blockIdx.z * sB;
    C += (size_t)blockIdx.z * sC;

    int rowStart = blockIdx.y * BM;
    int colStart = blockIdx.x * BN;
    int tid = threadIdx.x;
    int tr = (tid >> 4) * TM;
    int tc = (tid & 15) * TN;

    if (colStart > rowStart + (BM - 1)) {
        // Entire tile masked: write NEG, skip compute.
        float4 neg = make_float4(NEGV, NEGV, NEGV, NEGV);
#pragma unroll
        for (int i = 0; i < TM; i++) {
            int r = rowStart + tr + i;
#pragma unroll
            for (int j = 0; j < TN; j += 4)
                *(float4*)(C + (size_t)r * N + colStart + tc + j) = neg;
        }
        return;
    }

    int loadRow = tid >> 1;        // 0..127
    int loadCol = (tid & 1) * 4;   // 0 or 4

    float acc[TM][TN];
#pragma unroll
    for (int i = 0; i < TM; i++)
#pragma unroll
        for (int j = 0; j < TN; j++) acc[i][j] = 0.f;

    float rm[TM], rn[TN];
    for (int k0 = 0; k0 < K; k0 += BK) {
        float4 a = *(const float4*)(A + (size_t)(rowStart + loadRow) * K + k0 + loadCol);
        As[loadCol + 0][loadRow] = a.x;
        As[loadCol + 1][loadRow] = a.y;
        As[loadCol + 2][loadRow] = a.z;
        As[loadCol + 3][loadRow] = a.w;
        float4 b = *(const float4*)(B + (size_t)(colStart + loadRow) * K + k0 + loadCol);
        Bs[loadCol + 0][loadRow] = b.x;
        Bs[loadCol + 1][loadRow] = b.y;
        Bs[loadCol + 2][loadRow] = b.z;
        Bs[loadCol + 3][loadRow] = b.w;
        __syncthreads();
#pragma unroll
        for (int k = 0; k < BK; k++) {
#pragma unroll
            for (int i = 0; i < TM; i++) rm[i] = As[k][tr + i];
#pragma unroll
            for (int j = 0; j < TN; j++) rn[j] = Bs[k][tc + j];
#pragma unroll
            for (int i = 0; i < TM; i++)
#pragma unroll
                for (int j = 0; j < TN; j++) acc[i][j] += rm[i] * rn[j];
        }
        __syncthreads();
    }

#pragma unroll
    for (int i = 0; i < TM; i++) {
        int r = rowStart + tr + i;
#pragma unroll
        for (int j = 0; j < TN; j += 4) {
            float4 v;
            float* vp = &v.x;
#pragma unroll
            for (int q = 0; q < 4; q++) {
                int c = colStart + tc + j + q;
                float x = acc[i][j + q] * scale;
                if (c > r) x = NEGV;
                vp[q] = x;
            }
            *(float4*)(C + (size_t)r * N + colStart + tc + j) = v;
        }
    }
}

// ---------------------------------------------------------------------------
// Row softmax, in place. One block (256 thr) per row of SS=2048 floats.
// ---------------------------------------------------------------------------
__global__ void softmax_kernel(float* __restrict__ S) {
    __shared__ float red[256];
    int tid = threadIdx.x;
    float4* p = (float4*)(S + (size_t)blockIdx.x * SS);
    float4 a = p[tid];
    float4 b = p[tid + 256];

    float m = fmaxf(fmaxf(fmaxf(a.x, a.y), fmaxf(a.z, a.w)),
                    fmaxf(fmaxf(b.x, b.y), fmaxf(b.z, b.w)));
    red[tid] = m;
    __syncthreads();
    for (int s = 128; s > 0; s >>= 1) {
        if (tid < s) red[tid] = fmaxf(red[tid], red[tid + s]);
        __syncthreads();
    }
    m = red[0];
    __syncthreads();

    a.x = expf(a.x - m); a.y = expf(a.y - m); a.z = expf(a.z - m); a.w = expf(a.w - m);
    b.x = expf(b.x - m); b.y = expf(b.y - m); b.z = expf(b.z - m); b.w = expf(b.w - m);
    red[tid] = a.x + a.y + a.z + a.w + b.x + b.y + b.z + b.w;
    __syncthreads();
    for (int s = 128; s > 0; s >>= 1) {
        if (tid < s) red[tid] += red[tid + s];
        __syncthreads();
    }
    float inv = 1.0f / red[0];

    a.x *= inv; a.y *= inv; a.z *= inv; a.w *= inv;
    b.x *= inv; b.y *= inv; b.z *= inv; b.w *= inv;
    p[tid] = a;
    p[tid + 256] = b;
}

// ---------------------------------------------------------------------------
// LayerNorm (no scale/bias), E[x^2]-E[x]^2 variance, in place.
// One block (256 thr) per row of DD=1024 floats.
// ---------------------------------------------------------------------------
__global__ void layernorm_kernel(float* __restrict__ H) {
    __shared__ float red[256];
    int tid = threadIdx.x;
    float4* p = (float4*)(H + (size_t)blockIdx.x * DD);
    float4 v = p[tid];

    red[tid] = v.x + v.y + v.z + v.w;
    __syncthreads();
    for (int s = 128; s > 0; s >>= 1) {
        if (tid < s) red[tid] += red[tid + s];
        __syncthreads();
    }
    float mean = red[0] * (1.0f / DD);
    __syncthreads();

    red[tid] = v.x * v.x + v.y * v.y + v.z * v.z + v.w * v.w;
    __syncthreads();
    for (int s = 128; s > 0; s >>= 1) {
        if (tid < s) red[tid] += red[tid + s];
        __syncthreads();
    }
    float msq = red[0] * (1.0f / DD);

    float inv = 1.0f / sqrtf(msq - mean * mean + 1e-5f);
    v.x = (v.x - mean) * inv;
    v.y = (v.y - mean) * inv;
    v.z = (v.z - mean) * inv;
    v.w = (v.w - mean) * inv;
    p[tid] = v;
}

// ---------------------------------------------------------------------------
extern "C" void kernel_launch(void* const* d_in, const int* in_sizes, int n_in,
                              void* d_out, int out_size) {
    const float* x    = (const float*)d_in[0];
    // d_in[1] = mask (causal tril) — applied analytically, not read.
    const float* wi   = (const float*)d_in[2];
    const float* ok   = (const float*)d_in[3];
    const float* bias = (const float*)d_in[4];
    float* out = (float*)d_out;

    int H = in_sizes[3] / (DD * DD);  // 8

    float *q, *sc, *head, *h, *t, *w2;
    cudaGetSymbolAddress((void**)&q,    g_q);
    cudaGetSymbolAddress((void**)&sc,   g_scores);
    cudaGetSymbolAddress((void**)&head, g_head);
    cudaGetSymbolAddress((void**)&h,    g_h);
    cudaGetSymbolAddress((void**)&t,    g_t);
    cudaGetSymbolAddress((void**)&w2,   g_w2);

    const int M = BBATCH * SS;  // 4096

    // W2 = sum_h out_kernel slices
    w2_reduce_kernel<<<(DD * DD + 255) / 256, 256>>>(ok, w2, H);

    // q = x @ wi
    sgemm_nn<0><<<dim3(DD / 128, M / 128, 1), 256>>>(
        M, DD, DD, x, wi, q, nullptr, 0, 0, 0);

    // scores = (q @ q^T) / sqrt(D), causal mask
    sgemm_nt_scores<<<dim3(SS / 128, SS / 128, BBATCH), 256>>>(
        SS, SS, DD, q, q, sc, 1.0f / 32.0f,
        (long)SS * DD, (long)SS * DD, (long)SS * SS);

    // softmax rows
    softmax_kernel<<<BBATCH * SS, 256>>>(sc);

    // head = q + P @ q   (causal K-clamp inside, EPI=1)
    sgemm_nn<1><<<dim3(DD / 128, SS / 128, BBATCH), 256>>>(
        SS, DD, SS, sc, q, head, q,
        (long)SS * SS, (long)SS * DD, (long)SS * DD);

    // h = head @ W2 + bias
    sgemm_nn<2><<<dim3(DD / 128, M / 128, 1), 256>>>(
        M, DD, DD, head, w2, h, bias, 0, 0, 0);

    // LayerNorm in place
    layernorm_kernel<<<M, 256>>>(h);

    // t = swish(h @ wi)
    sgemm_nn<3><<<dim3(DD / 128, M / 128, 1), 256>>>(
        M, DD, DD, h, wi, t, nullptr, 0, 0, 0);

    // out = t @ wi
    sgemm_nn<0><<<dim3(DD / 128, M / 128, 1), 256>>>(
        M, DD, DD, t, wi, out, nullptr, 0, 0, 0);
}

// round 3
// speedup vs baseline: 2.1096x; 2.1096x over previous
#include <cuda_runtime.h>
#include <cuda_bf16.h>
#include <math.h>
#include <stdint.h>

// ---------------------------------------------------------------------------
// Problem constants
// ---------------------------------------------------------------------------
#define DD 1024
#define SS 2048
#define BB 2
#define MT (BB * SS)          // 4096
#define NEGV (-1e10f)

// ---------------------------------------------------------------------------
// Scratch (device globals; no allocation allowed)
// ---------------------------------------------------------------------------
__device__ __nv_bfloat16 g_xh[MT * DD], g_xl[MT * DD];
__device__ __nv_bfloat16 g_wth[DD * DD], g_wtl[DD * DD];     // wi^T hi/lo
__device__ float        g_w2[DD * DD];
__device__ __nv_bfloat16 g_w2th[DD * DD], g_w2tl[DD * DD];   // W2^T hi/lo
__device__ float        g_q[MT * DD];
__device__ __nv_bfloat16 g_qh[MT * DD], g_ql[MT * DD];
__device__ __nv_bfloat16 g_qth[MT * DD], g_qtl[MT * DD];     // q^T per batch
__device__ float        g_sc[(size_t)BB * SS * SS];
__device__ __nv_bfloat16 g_ph[(size_t)BB * SS * SS], g_pl[(size_t)BB * SS * SS];
__device__ __nv_bfloat16 g_heh[MT * DD], g_hel[MT * DD];     // head hi/lo
__device__ float        g_hn[MT * DD];                        // h (pre-LN)
__device__ __nv_bfloat16 g_nh[MT * DD], g_nl[MT * DD];       // LN(h) hi/lo
__device__ __nv_bfloat16 g_th[MT * DD], g_tl[MT * DD];       // swish out hi/lo

// ---------------------------------------------------------------------------
// PTX helpers (baseline ISA only — no arch-specific 'a' features)
// ---------------------------------------------------------------------------
__device__ __forceinline__ uint32_t smem_to_u32(const void* p) {
    uint32_t a;
    asm("{ .reg .u64 t; cvta.to.shared.u64 t, %1; cvt.u32.u64 %0, t; }"
        : "=r"(a) : "l"(p));
    return a;
}
__device__ __forceinline__ void cpasync16(uint32_t dst, const void* src) {
    asm volatile("cp.async.cg.shared.global [%0], [%1], 16;" :: "r"(dst), "l"(src));
}
#define CP_COMMIT() asm volatile("cp.async.commit_group;" ::: "memory")
#define CP_WAIT(n)  asm volatile("cp.async.wait_group %0;" :: "n"(n) : "memory")

__device__ __forceinline__ void ldsm4(uint32_t* r, uint32_t addr) {
    asm volatile("ldmatrix.sync.aligned.m8n8.x4.shared.b16 {%0,%1,%2,%3}, [%4];"
                 : "=r"(r[0]), "=r"(r[1]), "=r"(r[2]), "=r"(r[3]) : "r"(addr));
}
__device__ __forceinline__ void mma16816(float* c, const uint32_t* a, const uint32_t* b) {
    asm volatile(
        "mma.sync.aligned.m16n8k16.row.col.f32.bf16.bf16.f32 "
        "{%0,%1,%2,%3}, {%4,%5,%6,%7}, {%8,%9}, {%0,%1,%2,%3};"
        : "+f"(c[0]), "+f"(c[1]), "+f"(c[2]), "+f"(c[3])
        : "r"(a[0]), "r"(a[1]), "r"(a[2]), "r"(a[3]), "r"(b[0]), "r"(b[1]));
}

// ---------------------------------------------------------------------------
// fp32 -> bf16 hi/lo split
// ---------------------------------------------------------------------------
__device__ __forceinline__ void split1(float v, __nv_bfloat16& h, __nv_bfloat16& l) {
    h = __float2bfloat16(v);
    l = __float2bfloat16(v - __bfloat162float(h));
}

// ---------------------------------------------------------------------------
// Elementwise / reshape kernels
// ---------------------------------------------------------------------------
__global__ void split_kernel(const float* __restrict__ in,
                             __nv_bfloat16* __restrict__ oh,
                             __nv_bfloat16* __restrict__ ol, int n4) {
    int i = blockIdx.x * blockDim.x + threadIdx.x;
    if (i >= n4) return;
    float4 v = ((const float4*)in)[i];
    __nv_bfloat16 h, l;
    size_t b = (size_t)i * 4;
    split1(v.x, h, l); oh[b + 0] = h; ol[b + 0] = l;
    split1(v.y, h, l); oh[b + 1] = h; ol[b + 1] = l;
    split1(v.z, h, l); oh[b + 2] = h; ol[b + 2] = l;
    split1(v.w, h, l); oh[b + 3] = h; ol[b + 3] = l;
}

__global__ void transpose_split_kernel(const float* __restrict__ in,
                                       __nv_bfloat16* __restrict__ oh,
                                       __nv_bfloat16* __restrict__ ol,
                                       int R, int C, long sin, long sout) {
    __shared__ float t[32][33];
    in += (size_t)blockIdx.z * sin;
    oh += (size_t)blockIdx.z * sout;
    ol += (size_t)blockIdx.z * sout;
    int r0 = blockIdx.y * 32, c0 = blockIdx.x * 32;
    for (int i = threadIdx.y; i < 32; i += 8)
        t[i][threadIdx.x] = in[(size_t)(r0 + i) * C + c0 + threadIdx.x];
    __syncthreads();
    for (int i = threadIdx.y; i < 32; i += 8) {
        float v = t[threadIdx.x][i];
        __nv_bfloat16 h, l;
        split1(v, h, l);
        size_t o = (size_t)(c0 + i) * R + r0 + threadIdx.x;
        oh[o] = h; ol[o] = l;
    }
}

__global__ void w2_reduce_kernel(const float* __restrict__ ok,
                                 float* __restrict__ w2, int H) {
    int idx = blockIdx.x * blockDim.x + threadIdx.x;
    if (idx >= DD * DD) return;
    int i = idx / DD, j = idx % DD;
    float s = 0.f;
    for (int h = 0; h < H; h++) s += ok[(size_t)(h * DD + i) * DD + j];
    w2[idx] = s;
}

__global__ void softmax_kernel(const float* __restrict__ S,
                               __nv_bfloat16* __restrict__ ph,
                               __nv_bfloat16* __restrict__ pl) {
    __shared__ float red[256];
    int tid = threadIdx.x;
    size_t base = (size_t)blockIdx.x * SS;
    const float4* p = (const float4*)(S + base);
    float4 a = p[tid], b = p[tid + 256];

    float m = fmaxf(fmaxf(fmaxf(a.x, a.y), fmaxf(a.z, a.w)),
                    fmaxf(fmaxf(b.x, b.y), fmaxf(b.z, b.w)));
    red[tid] = m; __syncthreads();
    for (int s = 128; s > 0; s >>= 1) { if (tid < s) red[tid] = fmaxf(red[tid], red[tid + s]); __syncthreads(); }
    m = red[0]; __syncthreads();

    a.x = expf(a.x - m); a.y = expf(a.y - m); a.z = expf(a.z - m); a.w = expf(a.w - m);
    b.x = expf(b.x - m); b.y = expf(b.y - m); b.z = expf(b.z - m); b.w = expf(b.w - m);
    red[tid] = a.x + a.y + a.z + a.w + b.x + b.y + b.z + b.w; __syncthreads();
    for (int s = 128; s > 0; s >>= 1) { if (tid < s) red[tid] += red[tid + s]; __syncthreads(); }
    float inv = 1.0f / red[0];

    __nv_bfloat16 h, l;
    size_t o = base + (size_t)tid * 4;
    split1(a.x * inv, h, l); ph[o + 0] = h; pl[o + 0] = l;
    split1(a.y * inv, h, l); ph[o + 1] = h; pl[o + 1] = l;
    split1(a.z * inv, h, l); ph[o + 2] = h; pl[o + 2] = l;
    split1(a.w * inv, h, l); ph[o + 3] = h; pl[o + 3] = l;
    o = base + (size_t)(tid + 256) * 4;
    split1(b.x * inv, h, l); ph[o + 0] = h; pl[o + 0] = l;
    split1(b.y * inv, h, l); ph[o + 1] = h; pl[o + 1] = l;
    split1(b.z * inv, h, l); ph[o + 2] = h; pl[o + 2] = l;
    split1(b.w * inv, h, l); ph[o + 3] = h; pl[o + 3] = l;
}

__global__ void layernorm_kernel(const float* __restrict__ H,
                                 __nv_bfloat16* __restrict__ oh,
                                 __nv_bfloat16* __restrict__ ol) {
    __shared__ float red[256];
    int tid = threadIdx.x;
    size_t base = (size_t)blockIdx.x * DD;
    float4 v = ((const float4*)(H + base))[tid];

    red[tid] = v.x + v.y + v.z + v.w; __syncthreads();
    for (int s = 128; s > 0; s >>= 1) { if (tid < s) red[tid] += red[tid + s]; __syncthreads(); }
    float mean = red[0] * (1.0f / DD); __syncthreads();
    red[tid] = v.x * v.x + v.y * v.y + v.z * v.z + v.w * v.w; __syncthreads();
    for (int s = 128; s > 0; s >>= 1) { if (tid < s) red[tid] += red[tid + s]; __syncthreads(); }
    float msq = red[0] * (1.0f / DD);
    float inv = 1.0f / sqrtf(msq - mean * mean + 1e-5f);

    __nv_bfloat16 h, l;
    size_t o = base + (size_t)tid * 4;
    split1((v.x - mean) * inv, h, l); oh[o + 0] = h; ol[o + 0] = l;
    split1((v.y - mean) * inv, h, l); oh[o + 1] = h; ol[o + 1] = l;
    split1((v.z - mean) * inv, h, l); oh[o + 2] = h; ol[o + 2] = l;
    split1((v.w - mean) * inv, h, l); oh[o + 3] = h; ol[o + 3] = l;
}

// ---------------------------------------------------------------------------
// HMMA bf16 split GEMM: C[z] = A[z] @ B[z]^T  (A:[M,K], B:[N,K], hi/lo bf16)
// 128x128 block tile, BK=32, 8 warps (4 in M x 2 in N), warp tile 32x64.
// 3 HMMA per product group: Ah*Bh + Ah*Bl + Al*Bh, fp32 accumulate.
// ---------------------------------------------------------------------------
enum { EPI_F32 = 0, EPI_QOUT = 1, EPI_SCORES = 2, EPI_RESID = 3, EPI_BIAS = 4, EPI_SWISH = 5 };

#define LDS_T 40                        // smem row stride (bf16 elems): conflict-free ldmatrix
#define TEN_B (128 * LDS_T * 2)         // one tensor tile: 10240 B
#define BUF_B (4 * TEN_B)               // Ah, Al, Bh, Bl: 40960 B
#define SMEM_BYTES (2 * BUF_B)          // double buffered: 81920 B

__device__ __forceinline__ void load_tensor(uint32_t sdst, const __nv_bfloat16* g,
                                            int base_row, int ldK, int kofs, int tid) {
#pragma unroll
    for (int i = 0; i < 2; i++) {
        int v = tid * 2 + i;                 // 0..511
        int row = v >> 2, cseg = v & 3;      // 4 x 8-elem segments per 32-col row
        uint32_t dst = sdst + (uint32_t)(row * LDS_T + cseg * 8) * 2;
        cpasync16(dst, g + (size_t)(base_row + row) * ldK + kofs + cseg * 8);
    }
}

template <int EPI, bool CAUSAL, bool KCLAMP>
__global__ __launch_bounds__(256, 1) void gemm_tc(
    int M, int N, int K,
    const __nv_bfloat16* __restrict__ Ah, const __nv_bfloat16* __restrict__ Al,
    const __nv_bfloat16* __restrict__ Bh, const __nv_bfloat16* __restrict__ Bl,
    float* __restrict__ Cf,
    __nv_bfloat16* __restrict__ Ch, __nv_bfloat16* __restrict__ Cl,
    const float* __restrict__ Ef, float scale,
    long sA, long sB, long sC) {
    extern __shared__ char smem[];
    const int tid = threadIdx.x;
    const int rowStart = blockIdx.y * 128, colStart = blockIdx.x * 128;
    const int z = blockIdx.z;
    Ah += (size_t)z * sA; Al += (size_t)z * sA;
    Bh += (size_t)z * sB; Bl += (size_t)z * sB;
    const size_t cofs = (size_t)z * sC;

    if (CAUSAL && colStart > rowStart) {
        float4 neg = make_float4(NEGV, NEGV, NEGV, NEGV);
        for (int u = tid; u < 128 * 32; u += 256) {
            int r = u >> 5, c = (u & 31) * 4;
            *(float4*)(Cf + cofs + (size_t)(rowStart + r) * N + colStart + c) = neg;
        }
        return;
    }

    const uint32_t sb = smem_to_u32(smem);
    const int lane = tid & 31, wid = tid >> 5;
    const int warp_m = wid & 3, warp_n = wid >> 2;

    const int NC = (KCLAMP ? (rowStart + 128) : K) / 32;

    // ldmatrix source addresses (element offsets within a tensor tile)
    const int a_row = warp_m * 32 + (lane & 15);
    const int a_col = (lane >> 4) * 8;
    const int b_row = warp_n * 64 + (lane & 7) + ((lane >> 4) & 1) * 8;
    const int b_col = ((lane >> 3) & 1) * 8;

    float acc[2][8][4];
#pragma unroll
    for (int i = 0; i < 2; i++)
#pragma unroll
        for (int j = 0; j < 8; j++)
#pragma unroll
            for (int q = 0; q < 4; q++) acc[i][j][q] = 0.f;

    // prologue: chunk 0 -> buf 0
    load_tensor(sb + 0 * TEN_B, Ah, rowStart, K, 0, tid);
    load_tensor(sb + 1 * TEN_B, Al, rowStart, K, 0, tid);
    load_tensor(sb + 2 * TEN_B, Bh, colStart, K, 0, tid);
    load_tensor(sb + 3 * TEN_B, Bl, colStart, K, 0, tid);
    CP_COMMIT();

    for (int c = 0; c < NC; c++) {
        const uint32_t buf = sb + (uint32_t)(c & 1) * BUF_B;
        if (c + 1 < NC) {
            const uint32_t nbuf = sb + (uint32_t)((c + 1) & 1) * BUF_B;
            const int kofs = (c + 1) * 32;
            load_tensor(nbuf + 0 * TEN_B, Ah, rowStart, K, kofs, tid);
            load_tensor(nbuf + 1 * TEN_B, Al, rowStart, K, kofs, tid);
            load_tensor(nbuf + 2 * TEN_B, Bh, colStart, K, kofs, tid);
            load_tensor(nbuf + 3 * TEN_B, Bl, colStart, K, kofs, tid);
            CP_COMMIT();
            CP_WAIT(1);
        } else {
            CP_WAIT(0);
        }
        __syncthreads();

#pragma unroll
        for (int k0 = 0; k0 < 32; k0 += 16) {
            uint32_t ah[2][4], al[2][4], bh[4][4], bl[4][4];
#pragma unroll
            for (int mt = 0; mt < 2; mt++) {
                uint32_t ao = (uint32_t)((a_row + mt * 16) * LDS_T + k0 + a_col) * 2;
                ldsm4(ah[mt], buf + 0 * TEN_B + ao);
                ldsm4(al[mt], buf + 1 * TEN_B + ao);
            }
#pragma unroll
            for (int np = 0; np < 4; np++) {
                uint32_t bo = (uint32_t)((b_row + np * 16) * LDS_T + k0 + b_col) * 2;
                ldsm4(bh[np], buf + 2 * TEN_B + bo);
                ldsm4(bl[np], buf + 3 * TEN_B + bo);
            }
#pragma unroll
            for (int mt = 0; mt < 2; mt++)
#pragma unroll
                for (int np = 0; np < 4; np++) {
                    mma16816(acc[mt][2 * np + 0], ah[mt], &bh[np][0]);
                    mma16816(acc[mt][2 * np + 1], ah[mt], &bh[np][2]);
                    mma16816(acc[mt][2 * np + 0], ah[mt], &bl[np][0]);
                    mma16816(acc[mt][2 * np + 1], ah[mt], &bl[np][2]);
                    mma16816(acc[mt][2 * np + 0], al[mt], &bh[np][0]);
                    mma16816(acc[mt][2 * np + 1], al[mt], &bh[np][2]);
                }
        }
        __syncthreads();
    }

    // epilogue: registers -> gmem
#pragma unroll
    for (int mt = 0; mt < 2; mt++)
#pragma unroll
        for (int nt = 0; nt < 8; nt++) {
            const float* a = acc[mt][nt];
            int r0 = rowStart + warp_m * 32 + mt * 16 + (lane >> 2);
            int c0 = colStart + warp_n * 64 + nt * 8 + (lane & 3) * 2;
#pragma unroll
            for (int half = 0; half < 2; half++) {
                int gr = r0 + half * 8;
                float x0 = a[half * 2 + 0], x1 = a[half * 2 + 1];
                size_t o = cofs + (size_t)gr * N + c0;
                if (EPI == EPI_F32) {
                    *(float2*)(Cf + o) = make_float2(x0, x1);
                } else if (EPI == EPI_QOUT) {
                    *(float2*)(Cf + o) = make_float2(x0, x1);
                    __nv_bfloat16 h0, l0, h1, l1;
                    split1(x0, h0, l0); split1(x1, h1, l1);
                    *(__nv_bfloat162*)(Ch + o) = __nv_bfloat162(h0, h1);
                    *(__nv_bfloat162*)(Cl + o) = __nv_bfloat162(l0, l1);
                } else if (EPI == EPI_SCORES) {
                    x0 *= scale; x1 *= scale;
                    if (c0 + 0 > gr) x0 = NEGV;
                    if (c0 + 1 > gr) x1 = NEGV;
                    *(float2*)(Cf + o) = make_float2(x0, x1);
                } else if (EPI == EPI_RESID) {
                    float2 e = *(const float2*)(Ef + o);
                    x0 += e.x; x1 += e.y;
                    __nv_bfloat16 h0, l0, h1, l1;
                    split1(x0, h0, l0); split1(x1, h1, l1);
                    *(__nv_bfloat162*)(Ch + o) = __nv_bfloat162(h0, h1);
                    *(__nv_bfloat162*)(Cl + o) = __nv_bfloat162(l0, l1);
                } else if (EPI == EPI_BIAS) {
                    x0 += Ef[c0]; x1 += Ef[c0 + 1];
                    *(float2*)(Cf + o) = make_float2(x0, x1);
                } else if (EPI == EPI_SWISH) {
                    x0 = x0 / (1.f + expf(-x0));
                    x1 = x1 / (1.f + expf(-x1));
                    __nv_bfloat16 h0, l0, h1, l1;
                    split1(x0, h0, l0); split1(x1, h1, l1);
                    *(__nv_bfloat162*)(Ch + o) = __nv_bfloat162(h0, h1);
                    *(__nv_bfloat162*)(Cl + o) = __nv_bfloat162(l0, l1);
                }
            }
        }
}

// ---------------------------------------------------------------------------
extern "C" void kernel_launch(void* const* d_in, const int* in_sizes, int n_in,
                              void* d_out, int out_size) {
    const float* x    = (const float*)d_in[0];
    const float* wi   = (const float*)d_in[2];
    const float* ok   = (const float*)d_in[3];
    const float* bias = (const float*)d_in[4];
    float* out = (float*)d_out;
    int H = in_sizes[3] / (DD * DD);

    float *q, *w2, *sc, *hn;
    __nv_bfloat16 *xh, *xl, *wth, *wtl, *w2th, *w2tl, *qh, *ql, *qth, *qtl;
    __nv_bfloat16 *pph, *ppl, *heh, *hel, *nh, *nl, *th, *tl;
    cudaGetSymbolAddress((void**)&q,    g_q);
    cudaGetSymbolAddress((void**)&w2,   g_w2);
    cudaGetSymbolAddress((void**)&sc,   g_sc);
    cudaGetSymbolAddress((void**)&hn,   g_hn);
    cudaGetSymbolAddress((void**)&xh,   g_xh);   cudaGetSymbolAddress((void**)&xl,   g_xl);
    cudaGetSymbolAddress((void**)&wth,  g_wth);  cudaGetSymbolAddress((void**)&wtl,  g_wtl);
    cudaGetSymbolAddress((void**)&w2th, g_w2th); cudaGetSymbolAddress((void**)&w2tl, g_w2tl);
    cudaGetSymbolAddress((void**)&qh,   g_qh);   cudaGetSymbolAddress((void**)&ql,   g_ql);
    cudaGetSymbolAddress((void**)&qth,  g_qth);  cudaGetSymbolAddress((void**)&qtl,  g_qtl);
    cudaGetSymbolAddress((void**)&pph,  g_ph);   cudaGetSymbolAddress((void**)&ppl,  g_pl);
    cudaGetSymbolAddress((void**)&heh,  g_heh);  cudaGetSymbolAddress((void**)&hel,  g_hel);
    cudaGetSymbolAddress((void**)&nh,   g_nh);   cudaGetSymbolAddress((void**)&nl,   g_nl);
    cudaGetSymbolAddress((void**)&th,   g_th);   cudaGetSymbolAddress((void**)&tl,   g_tl);

    cudaFuncSetAttribute((const void*)gemm_tc<EPI_QOUT,   false, false>, cudaFuncAttributeMaxDynamicSharedMemorySize, SMEM_BYTES);
    cudaFuncSetAttribute((const void*)gemm_tc<EPI_SCORES, true,  false>, cudaFuncAttributeMaxDynamicSharedMemorySize, SMEM_BYTES);
    cudaFuncSetAttribute((const void*)gemm_tc<EPI_RESID,  false, true >, cudaFuncAttributeMaxDynamicSharedMemorySize, SMEM_BYTES);
    cudaFuncSetAttribute((const void*)gemm_tc<EPI_BIAS,   false, false>, cudaFuncAttributeMaxDynamicSharedMemorySize, SMEM_BYTES);
    cudaFuncSetAttribute((const void*)gemm_tc<EPI_SWISH,  false, false>, cudaFuncAttributeMaxDynamicSharedMemorySize, SMEM_BYTES);
    cudaFuncSetAttribute((const void*)gemm_tc<EPI_F32,    false, false>, cudaFuncAttributeMaxDynamicSharedMemorySize, SMEM_BYTES);

    // --- preprocessing ---
    split_kernel<<<(MT * DD / 4 + 255) / 256, 256>>>(x, xh, xl, MT * DD / 4);
    transpose_split_kernel<<<dim3(32, 32, 1), dim3(32, 8)>>>(wi, wth, wtl, DD, DD, 0, 0);
    w2_reduce_kernel<<<(DD * DD + 255) / 256, 256>>>(ok, w2, H);
    transpose_split_kernel<<<dim3(32, 32, 1), dim3(32, 8)>>>(w2, w2th, w2tl, DD, DD, 0, 0);

    // q = x @ wi  (B = wi^T)  -> q fp32 + hi/lo
    gemm_tc<EPI_QOUT, false, false><<<dim3(DD / 128, MT / 128, 1), 256, SMEM_BYTES>>>(
        MT, DD, DD, xh, xl, wth, wtl, q, qh, ql, nullptr, 0.f, 0, 0, 0);

    // q^T per batch (B operand for P@V)
    transpose_split_kernel<<<dim3(32, 64, BB), dim3(32, 8)>>>(
        q, qth, qtl, SS, DD, (long)SS * DD, (long)SS * DD);

    // scores = (q @ q^T)/32, causal -> fp32
    gemm_tc<EPI_SCORES, true, false><<<dim3(SS / 128, SS / 128, BB), 256, SMEM_BYTES>>>(
        SS, SS, DD, qh, ql, qh, ql, sc, nullptr, nullptr, nullptr, 1.0f / 32.0f,
        (long)SS * DD, (long)SS * DD, (long)SS * SS);

    // softmax -> P hi/lo
    softmax_kernel<<<BB * SS, 256>>>(sc, pph, ppl);

    // head = q + P @ q   (B = q^T, causal K clamp) -> head hi/lo
    gemm_tc<EPI_RESID, false, true><<<dim3(DD / 128, SS / 128, BB), 256, SMEM_BYTES>>>(
        SS, DD, SS, pph, ppl, qth, qtl, nullptr, heh, hel, q, 0.f,
        (long)SS * SS, (long)SS * DD, (long)SS * DD);

    // h = head @ W2 + bias -> fp32
    gemm_tc<EPI_BIAS, false, false><<<dim3(DD / 128, MT / 128, 1), 256, SMEM_BYTES>>>(
        MT, DD, DD, heh, hel, w2th, w2tl, hn, nullptr, nullptr, bias, 0.f, 0, 0, 0);

    // LayerNorm -> hi/lo
    layernorm_kernel<<<MT, 256>>>(hn, nh, nl);

    // t = swish(h @ wi) -> hi/lo
    gemm_tc<EPI_SWISH, false, false><<<dim3(DD / 128, MT / 128, 1), 256, SMEM_BYTES>>>(
        MT, DD, DD, nh, nl, wth, wtl, nullptr, th, tl, nullptr, 0.f, 0, 0, 0);

    // out = t @ wi -> fp32
    gemm_tc<EPI_F32, false, false><<<dim3(DD / 128, MT / 128, 1), 256, SMEM_BYTES>>>(
        MT, DD, DD, th, tl, wth, wtl, out, nullptr, nullptr, nullptr, 0.f, 0, 0, 0);
}

// round 4
// speedup vs baseline: 2.2002x; 1.0429x over previous
#include <cuda_runtime.h>
#include <cuda_bf16.h>
#include <math.h>
#include <stdint.h>

// ---------------------------------------------------------------------------
// Problem constants
// ---------------------------------------------------------------------------
#define DD 1024
#define SS 2048
#define BB 2
#define MT (BB * SS)          // 4096
#define NEGV (-1e10f)

// ---------------------------------------------------------------------------
// Scratch (device globals; no allocation allowed)
// ---------------------------------------------------------------------------
__device__ __nv_bfloat16 g_xh[MT * DD], g_xl[MT * DD];
__device__ __nv_bfloat16 g_wth[DD * DD], g_wtl[DD * DD];     // wi^T hi/lo
__device__ float        g_w2[DD * DD];
__device__ __nv_bfloat16 g_w2th[DD * DD], g_w2tl[DD * DD];   // W2^T hi/lo
__device__ float        g_q[MT * DD];
__device__ __nv_bfloat16 g_qh[MT * DD], g_ql[MT * DD];
__device__ __nv_bfloat16 g_qth[MT * DD], g_qtl[MT * DD];     // q^T per batch
__device__ float        g_sc[(size_t)BB * SS * SS];
__device__ __nv_bfloat16 g_ph[(size_t)BB * SS * SS], g_pl[(size_t)BB * SS * SS];
__device__ __nv_bfloat16 g_heh[MT * DD], g_hel[MT * DD];     // head hi/lo
__device__ float        g_hn[MT * DD];                        // h (pre-LN)
__device__ __nv_bfloat16 g_nh[MT * DD], g_nl[MT * DD];       // LN(h) hi/lo
__device__ __nv_bfloat16 g_th[MT * DD], g_tl[MT * DD];       // swish out hi/lo

// ---------------------------------------------------------------------------
// PTX helpers (baseline ISA only)
// ---------------------------------------------------------------------------
__device__ __forceinline__ uint32_t smem_to_u32(const void* p) {
    uint32_t a;
    asm("{ .reg .u64 t; cvta.to.shared.u64 t, %1; cvt.u32.u64 %0, t; }"
        : "=r"(a) : "l"(p));
    return a;
}
__device__ __forceinline__ void cpasync16(uint32_t dst, const void* src) {
    asm volatile("cp.async.cg.shared.global [%0], [%1], 16;" :: "r"(dst), "l"(src));
}
#define CP_COMMIT() asm volatile("cp.async.commit_group;" ::: "memory")
#define CP_WAIT(n)  asm volatile("cp.async.wait_group %0;" :: "n"(n) : "memory")

__device__ __forceinline__ void ldsm4(uint32_t* r, uint32_t addr) {
    asm volatile("ldmatrix.sync.aligned.m8n8.x4.shared.b16 {%0,%1,%2,%3}, [%4];"
                 : "=r"(r[0]), "=r"(r[1]), "=r"(r[2]), "=r"(r[3]) : "r"(addr));
}
__device__ __forceinline__ void mma16816(float* c, const uint32_t* a, const uint32_t* b) {
    asm volatile(
        "mma.sync.aligned.m16n8k16.row.col.f32.bf16.bf16.f32 "
        "{%0,%1,%2,%3}, {%4,%5,%6,%7}, {%8,%9}, {%0,%1,%2,%3};"
        : "+f"(c[0]), "+f"(c[1]), "+f"(c[2]), "+f"(c[3])
        : "r"(a[0]), "r"(a[1]), "r"(a[2]), "r"(a[3]), "r"(b[0]), "r"(b[1]));
}

// ---------------------------------------------------------------------------
// fp32 -> bf16 hi/lo split
// ---------------------------------------------------------------------------
__device__ __forceinline__ void split1(float v, __nv_bfloat16& h, __nv_bfloat16& l) {
    h = __float2bfloat16(v);
    l = __float2bfloat16(v - __bfloat162float(h));
}

// ---------------------------------------------------------------------------
// Elementwise / reshape kernels
// ---------------------------------------------------------------------------
__global__ void split_kernel(const float* __restrict__ in,
                             __nv_bfloat16* __restrict__ oh,
                             __nv_bfloat16* __restrict__ ol, int n4) {
    int i = blockIdx.x * blockDim.x + threadIdx.x;
    if (i >= n4) return;
    float4 v = ((const float4*)in)[i];
    __nv_bfloat16 h, l;
    size_t b = (size_t)i * 4;
    split1(v.x, h, l); oh[b + 0] = h; ol[b + 0] = l;
    split1(v.y, h, l); oh[b + 1] = h; ol[b + 1] = l;
    split1(v.z, h, l); oh[b + 2] = h; ol[b + 2] = l;
    split1(v.w, h, l); oh[b + 3] = h; ol[b + 3] = l;
}

__global__ void transpose_split_kernel(const float* __restrict__ in,
                                       __nv_bfloat16* __restrict__ oh,
                                       __nv_bfloat16* __restrict__ ol,
                                       int R, int C, long sin, long sout) {
    __shared__ float t[32][33];
    in += (size_t)blockIdx.z * sin;
    oh += (size_t)blockIdx.z * sout;
    ol += (size_t)blockIdx.z * sout;
    int r0 = blockIdx.y * 32, c0 = blockIdx.x * 32;
    for (int i = threadIdx.y; i < 32; i += 8)
        t[i][threadIdx.x] = in[(size_t)(r0 + i) * C + c0 + threadIdx.x];
    __syncthreads();
    for (int i = threadIdx.y; i < 32; i += 8) {
        float v = t[threadIdx.x][i];
        __nv_bfloat16 h, l;
        split1(v, h, l);
        size_t o = (size_t)(c0 + i) * R + r0 + threadIdx.x;
        oh[o] = h; ol[o] = l;
    }
}

__global__ void w2_reduce_kernel(const float* __restrict__ ok,
                                 float* __restrict__ w2, int H) {
    int idx = blockIdx.x * blockDim.x + threadIdx.x;
    if (idx >= DD * DD) return;
    int i = idx / DD, j = idx % DD;
    float s = 0.f;
    for (int h = 0; h < H; h++) s += ok[(size_t)(h * DD + i) * DD + j];
    w2[idx] = s;
}

// Causal softmax. One block per (batch,row). Reads only cols [0, L) of the
// scores row (the GEMM never writes the masked region), writes P hi/lo for
// cols [0, Kc) where Kc = ceil128(L); zeros beyond L. P@V clamps K to Kc.
__global__ void softmax_kernel(const float* __restrict__ S,
                               __nv_bfloat16* __restrict__ ph,
                               __nv_bfloat16* __restrict__ pl) {
    __shared__ float red[256];
    const int tid = threadIdx.x;
    const int L = (blockIdx.x & (SS - 1)) + 1;
    const int Kc = (L + 127) & ~127;
    const size_t base = (size_t)blockIdx.x * SS;

    float vals[8];
    float m = -3.0e38f;
    int n = 0;
    for (int c = tid; c < L; c += 256) {
        float v = S[base + c];
        vals[n++] = v;
        m = fmaxf(m, v);
    }
    red[tid] = m; __syncthreads();
    for (int s = 128; s > 0; s >>= 1) { if (tid < s) red[tid] = fmaxf(red[tid], red[tid + s]); __syncthreads(); }
    m = red[0]; __syncthreads();

    float sum = 0.f;
#pragma unroll 8
    for (int i = 0; i < n; i++) { vals[i] = expf(vals[i] - m); sum += vals[i]; }
    red[tid] = sum; __syncthreads();
    for (int s = 128; s > 0; s >>= 1) { if (tid < s) red[tid] += red[tid + s]; __syncthreads(); }
    float inv = 1.0f / red[0];

    n = 0;
    for (int c = tid; c < Kc; c += 256) {
        float p = (c < L) ? vals[n] * inv : 0.f;
        if (c < L) n++;
        __nv_bfloat16 h, l;
        split1(p, h, l);
        ph[base + c] = h; pl[base + c] = l;
    }
}

__global__ void layernorm_kernel(const float* __restrict__ H,
                                 __nv_bfloat16* __restrict__ oh,
                                 __nv_bfloat16* __restrict__ ol) {
    __shared__ float red[256];
    int tid = threadIdx.x;
    size_t base = (size_t)blockIdx.x * DD;
    float4 v = ((const float4*)(H + base))[tid];

    red[tid] = v.x + v.y + v.z + v.w; __syncthreads();
    for (int s = 128; s > 0; s >>= 1) { if (tid < s) red[tid] += red[tid + s]; __syncthreads(); }
    float mean = red[0] * (1.0f / DD); __syncthreads();
    red[tid] = v.x * v.x + v.y * v.y + v.z * v.z + v.w * v.w; __syncthreads();
    for (int s = 128; s > 0; s >>= 1) { if (tid < s) red[tid] += red[tid + s]; __syncthreads(); }
    float msq = red[0] * (1.0f / DD);
    float inv = 1.0f / sqrtf(msq - mean * mean + 1e-5f);

    __nv_bfloat16 h, l;
    size_t o = base + (size_t)tid * 4;
    split1((v.x - mean) * inv, h, l); oh[o + 0] = h; ol[o + 0] = l;
    split1((v.y - mean) * inv, h, l); oh[o + 1] = h; ol[o + 1] = l;
    split1((v.z - mean) * inv, h, l); oh[o + 2] = h; ol[o + 2] = l;
    split1((v.w - mean) * inv, h, l); oh[o + 3] = h; ol[o + 3] = l;
}

// ---------------------------------------------------------------------------
// HMMA bf16 split GEMM: C[z] = A[z] @ B[z]^T  (A:[M,K], B:[N,K], hi/lo bf16)
// 128x128 block tile, BK=32, 8 warps (4 in M x 2 in N), warp tile 32x64.
// 3-stage cp.async pipeline; split MMAs issued in 3 passes (hh, hl, lh) so
// each accumulator is re-touched only after 16 intervening MMAs.
// ---------------------------------------------------------------------------
enum { EPI_F32 = 0, EPI_QOUT = 1, EPI_SCORES = 2, EPI_RESID = 3, EPI_BIAS = 4, EPI_SWISH = 5 };

#define LDS_T 40                        // smem row stride (bf16): conflict-free ldmatrix
#define TEN_B (128 * LDS_T * 2)         // one tensor tile: 10240 B
#define BUF_B (4 * TEN_B)               // Ah, Al, Bh, Bl per stage: 40960 B
#define STAGES 3
#define SMEM_BYTES (STAGES * BUF_B)     // 122880 B

__device__ __forceinline__ void load_tensor(uint32_t sdst, const __nv_bfloat16* g,
                                            int base_row, int ldK, int kofs, int tid) {
#pragma unroll
    for (int i = 0; i < 2; i++) {
        int v = tid * 2 + i;                 // 0..511
        int row = v >> 2, cseg = v & 3;
        uint32_t dst = sdst + (uint32_t)(row * LDS_T + cseg * 8) * 2;
        cpasync16(dst, g + (size_t)(base_row + row) * ldK + kofs + cseg * 8);
    }
}

template <int EPI, bool CAUSAL, bool KCLAMP>
__global__ __launch_bounds__(256, 1) void gemm_tc(
    int M, int N, int K,
    const __nv_bfloat16* __restrict__ Ah, const __nv_bfloat16* __restrict__ Al,
    const __nv_bfloat16* __restrict__ Bh, const __nv_bfloat16* __restrict__ Bl,
    float* __restrict__ Cf,
    __nv_bfloat16* __restrict__ Ch, __nv_bfloat16* __restrict__ Cl,
    const float* __restrict__ Ef, float scale,
    long sA, long sB, long sC) {
    extern __shared__ char smem[];
    const int tid = threadIdx.x;
    const int rowStart = blockIdx.y * 128, colStart = blockIdx.x * 128;
    const int z = blockIdx.z;

    // Fully masked score tile: nothing to do (softmax never reads it).
    if (CAUSAL && colStart > rowStart) return;

    Ah += (size_t)z * sA; Al += (size_t)z * sA;
    Bh += (size_t)z * sB; Bl += (size_t)z * sB;
    const size_t cofs = (size_t)z * sC;

    const uint32_t sb = smem_to_u32(smem);
    const int lane = tid & 31, wid = tid >> 5;
    const int warp_m = wid & 3, warp_n = wid >> 2;

    const int NC = (KCLAMP ? (rowStart + 128) : K) / 32;

    const int a_row = warp_m * 32 + (lane & 15);
    const int a_col = (lane >> 4) * 8;
    const int b_row = warp_n * 64 + (lane & 7) + ((lane >> 4) & 1) * 8;
    const int b_col = ((lane >> 3) & 1) * 8;

    float acc[2][8][4];
#pragma unroll
    for (int i = 0; i < 2; i++)
#pragma unroll
        for (int j = 0; j < 8; j++)
#pragma unroll
            for (int q = 0; q < 4; q++) acc[i][j][q] = 0.f;

    // prologue: stage 0, 1
    {
        load_tensor(sb + 0 * TEN_B, Ah, rowStart, K, 0, tid);
        load_tensor(sb + 1 * TEN_B, Al, rowStart, K, 0, tid);
        load_tensor(sb + 2 * TEN_B, Bh, colStart, K, 0, tid);
        load_tensor(sb + 3 * TEN_B, Bl, colStart, K, 0, tid);
        CP_COMMIT();
        if (NC > 1) {
            load_tensor(sb + BUF_B + 0 * TEN_B, Ah, rowStart, K, 32, tid);
            load_tensor(sb + BUF_B + 1 * TEN_B, Al, rowStart, K, 32, tid);
            load_tensor(sb + BUF_B + 2 * TEN_B, Bh, colStart, K, 32, tid);
            load_tensor(sb + BUF_B + 3 * TEN_B, Bl, colStart, K, 32, tid);
            CP_COMMIT();
        }
    }

    int bufIdx = 0;
    for (int c = 0; c < NC; c++) {
        if (c + 1 < NC) { CP_WAIT(1); } else { CP_WAIT(0); }
        __syncthreads();

        if (c + 2 < NC) {
            int nIdx = bufIdx + 2; if (nIdx >= STAGES) nIdx -= STAGES;
            const uint32_t nbuf = sb + (uint32_t)nIdx * BUF_B;
            const int kofs = (c + 2) * 32;
            load_tensor(nbuf + 0 * TEN_B, Ah, rowStart, K, kofs, tid);
            load_tensor(nbuf + 1 * TEN_B, Al, rowStart, K, kofs, tid);
            load_tensor(nbuf + 2 * TEN_B, Bh, colStart, K, kofs, tid);
            load_tensor(nbuf + 3 * TEN_B, Bl, colStart, K, kofs, tid);
            CP_COMMIT();
        }

        const uint32_t buf = sb + (uint32_t)bufIdx * BUF_B;
#pragma unroll
        for (int k0 = 0; k0 < 32; k0 += 16) {
            uint32_t ah[2][4], al[2][4], bh[4][4], bl[4][4];
#pragma unroll
            for (int mt = 0; mt < 2; mt++) {
                uint32_t ao = (uint32_t)((a_row + mt * 16) * LDS_T + k0 + a_col) * 2;
                ldsm4(ah[mt], buf + 0 * TEN_B + ao);
                ldsm4(al[mt], buf + 1 * TEN_B + ao);
            }
#pragma unroll
            for (int np = 0; np < 4; np++) {
                uint32_t bo = (uint32_t)((b_row + np * 16) * LDS_T + k0 + b_col) * 2;
                ldsm4(bh[np], buf + 2 * TEN_B + bo);
                ldsm4(bl[np], buf + 3 * TEN_B + bo);
            }
            // pass 1: hh
#pragma unroll
            for (int mt = 0; mt < 2; mt++)
#pragma unroll
                for (int np = 0; np < 4; np++) {
                    mma16816(acc[mt][2 * np + 0], ah[mt], &bh[np][0]);
                    mma16816(acc[mt][2 * np + 1], ah[mt], &bh[np][2]);
                }
            // pass 2: hl
#pragma unroll
            for (int mt = 0; mt < 2; mt++)
#pragma unroll
                for (int np = 0; np < 4; np++) {
                    mma16816(acc[mt][2 * np + 0], ah[mt], &bl[np][0]);
                    mma16816(acc[mt][2 * np + 1], ah[mt], &bl[np][2]);
                }
            // pass 3: lh
#pragma unroll
            for (int mt = 0; mt < 2; mt++)
#pragma unroll
                for (int np = 0; np < 4; np++) {
                    mma16816(acc[mt][2 * np + 0], al[mt], &bh[np][0]);
                    mma16816(acc[mt][2 * np + 1], al[mt], &bh[np][2]);
                }
        }
        bufIdx++; if (bufIdx >= STAGES) bufIdx = 0;
    }

    // epilogue: registers -> gmem
#pragma unroll
    for (int mt = 0; mt < 2; mt++)
#pragma unroll
        for (int nt = 0; nt < 8; nt++) {
            const float* a = acc[mt][nt];
            int r0 = rowStart + warp_m * 32 + mt * 16 + (lane >> 2);
            int c0 = colStart + warp_n * 64 + nt * 8 + (lane & 3) * 2;
#pragma unroll
            for (int half = 0; half < 2; half++) {
                int gr = r0 + half * 8;
                float x0 = a[half * 2 + 0], x1 = a[half * 2 + 1];
                size_t o = cofs + (size_t)gr * N + c0;
                if (EPI == EPI_F32) {
                    *(float2*)(Cf + o) = make_float2(x0, x1);
                } else if (EPI == EPI_QOUT) {
                    *(float2*)(Cf + o) = make_float2(x0, x1);
                    __nv_bfloat16 h0, l0, h1, l1;
                    split1(x0, h0, l0); split1(x1, h1, l1);
                    *(__nv_bfloat162*)(Ch + o) = __nv_bfloat162(h0, h1);
                    *(__nv_bfloat162*)(Cl + o) = __nv_bfloat162(l0, l1);
                } else if (EPI == EPI_SCORES) {
                    // masked entries (col > row) may be garbage; softmax never
                    // reads them.
                    *(float2*)(Cf + o) = make_float2(x0 * scale, x1 * scale);
                } else if (EPI == EPI_RESID) {
                    float2 e = *(const float2*)(Ef + o);
                    x0 += e.x; x1 += e.y;
                    __nv_bfloat16 h0, l0, h1, l1;
                    split1(x0, h0, l0); split1(x1, h1, l1);
                    *(__nv_bfloat162*)(Ch + o) = __nv_bfloat162(h0, h1);
                    *(__nv_bfloat162*)(Cl + o) = __nv_bfloat162(l0, l1);
                } else if (EPI == EPI_BIAS) {
                    x0 += Ef[c0]; x1 += Ef[c0 + 1];
                    *(float2*)(Cf + o) = make_float2(x0, x1);
                } else if (EPI == EPI_SWISH) {
                    x0 = x0 / (1.f + expf(-x0));
                    x1 = x1 / (1.f + expf(-x1));
                    __nv_bfloat16 h0, l0, h1, l1;
                    split1(x0, h0, l0); split1(x1, h1, l1);
                    *(__nv_bfloat162*)(Ch + o) = __nv_bfloat162(h0, h1);
                    *(__nv_bfloat162*)(Cl + o) = __nv_bfloat162(l0, l1);
                }
            }
        }
}

// ---------------------------------------------------------------------------
extern "C" void kernel_launch(void* const* d_in, const int* in_sizes, int n_in,
                              void* d_out, int out_size) {
    const float* x    = (const float*)d_in[0];
    const float* wi   = (const float*)d_in[2];
    const float* ok   = (const float*)d_in[3];
    const float* bias = (const float*)d_in[4];
    float* out = (float*)d_out;
    int H = in_sizes[3] / (DD * DD);

    float *q, *w2, *sc, *hn;
    __nv_bfloat16 *xh, *xl, *wth, *wtl, *w2th, *w2tl, *qh, *ql, *qth, *qtl;
    __nv_bfloat16 *pph, *ppl, *heh, *hel, *nh, *nl, *th, *tl;
    cudaGetSymbolAddress((void**)&q,    g_q);
    cudaGetSymbolAddress((void**)&w2,   g_w2);
    cudaGetSymbolAddress((void**)&sc,   g_sc);
    cudaGetSymbolAddress((void**)&hn,   g_hn);
    cudaGetSymbolAddress((void**)&xh,   g_xh);   cudaGetSymbolAddress((void**)&xl,   g_xl);
    cudaGetSymbolAddress((void**)&wth,  g_wth);  cudaGetSymbolAddress((void**)&wtl,  g_wtl);
    cudaGetSymbolAddress((void**)&w2th, g_w2th); cudaGetSymbolAddress((void**)&w2tl, g_w2tl);
    cudaGetSymbolAddress((void**)&qh,   g_qh);   cudaGetSymbolAddress((void**)&ql,   g_ql);
    cudaGetSymbolAddress((void**)&qth,  g_qth);  cudaGetSymbolAddress((void**)&qtl,  g_qtl);
    cudaGetSymbolAddress((void**)&pph,  g_ph);   cudaGetSymbolAddress((void**)&ppl,  g_pl);
    cudaGetSymbolAddress((void**)&heh,  g_heh);  cudaGetSymbolAddress((void**)&hel,  g_hel);
    cudaGetSymbolAddress((void**)&nh,   g_nh);   cudaGetSymbolAddress((void**)&nl,   g_nl);
    cudaGetSymbolAddress((void**)&th,   g_th);   cudaGetSymbolAddress((void**)&tl,   g_tl);

    cudaFuncSetAttribute((const void*)gemm_tc<EPI_QOUT,   false, false>, cudaFuncAttributeMaxDynamicSharedMemorySize, SMEM_BYTES);
    cudaFuncSetAttribute((const void*)gemm_tc<EPI_SCORES, true,  false>, cudaFuncAttributeMaxDynamicSharedMemorySize, SMEM_BYTES);
    cudaFuncSetAttribute((const void*)gemm_tc<EPI_RESID,  false, true >, cudaFuncAttributeMaxDynamicSharedMemorySize, SMEM_BYTES);
    cudaFuncSetAttribute((const void*)gemm_tc<EPI_BIAS,   false, false>, cudaFuncAttributeMaxDynamicSharedMemorySize, SMEM_BYTES);
    cudaFuncSetAttribute((const void*)gemm_tc<EPI_SWISH,  false, false>, cudaFuncAttributeMaxDynamicSharedMemorySize, SMEM_BYTES);
    cudaFuncSetAttribute((const void*)gemm_tc<EPI_F32,    false, false>, cudaFuncAttributeMaxDynamicSharedMemorySize, SMEM_BYTES);

    // --- preprocessing ---
    split_kernel<<<(MT * DD / 4 + 255) / 256, 256>>>(x, xh, xl, MT * DD / 4);
    transpose_split_kernel<<<dim3(32, 32, 1), dim3(32, 8)>>>(wi, wth, wtl, DD, DD, 0, 0);
    w2_reduce_kernel<<<(DD * DD + 255) / 256, 256>>>(ok, w2, H);
    transpose_split_kernel<<<dim3(32, 32, 1), dim3(32, 8)>>>(w2, w2th, w2tl, DD, DD, 0, 0);

    // q = x @ wi  (B = wi^T)  -> q fp32 + hi/lo
    gemm_tc<EPI_QOUT, false, false><<<dim3(DD / 128, MT / 128, 1), 256, SMEM_BYTES>>>(
        MT, DD, DD, xh, xl, wth, wtl, q, qh, ql, nullptr, 0.f, 0, 0, 0);

    // q^T per batch (B operand for P@V)
    transpose_split_kernel<<<dim3(32, 64, BB), dim3(32, 8)>>>(
        q, qth, qtl, SS, DD, (long)SS * DD, (long)SS * DD);

    // scores = (q @ q^T)/32  (lower-triangle tiles only do work)
    gemm_tc<EPI_SCORES, true, false><<<dim3(SS / 128, SS / 128, BB), 256, SMEM_BYTES>>>(
        SS, SS, DD, qh, ql, qh, ql, sc, nullptr, nullptr, nullptr, 1.0f / 32.0f,
        (long)SS * DD, (long)SS * DD, (long)SS * SS);

    // causal softmax -> P hi/lo (zeros to 128-padded boundary)
    softmax_kernel<<<BB * SS, 256>>>(sc, pph, ppl);

    // head = q + P @ q   (B = q^T, causal K clamp) -> head hi/lo
    gemm_tc<EPI_RESID, false, true><<<dim3(DD / 128, SS / 128, BB), 256, SMEM_BYTES>>>(
        SS, DD, SS, pph, ppl, qth, qtl, nullptr, heh, hel, q, 0.f,
        (long)SS * SS, (long)SS * DD, (long)SS * DD);

    // h = head @ W2 + bias -> fp32
    gemm_tc<EPI_BIAS, false, false><<<dim3(DD / 128, MT / 128, 1), 256, SMEM_BYTES>>>(
        MT, DD, DD, heh, hel, w2th, w2tl, hn, nullptr, nullptr, bias, 0.f, 0, 0, 0);

    // LayerNorm -> hi/lo
    layernorm_kernel<<<MT, 256>>>(hn, nh, nl);

    // t = swish(h @ wi) -> hi/lo
    gemm_tc<EPI_SWISH, false, false><<<dim3(DD / 128, MT / 128, 1), 256, SMEM_BYTES>>>(
        MT, DD, DD, nh, nl, wth, wtl, nullptr, th, tl, nullptr, 0.f, 0, 0, 0);

    // out = t @ wi -> fp32
    gemm_tc<EPI_F32, false, false><<<dim3(DD / 128, MT / 128, 1), 256, SMEM_BYTES>>>(
        MT, DD, DD, th, tl, wth, wtl, out, nullptr, nullptr, nullptr, 0.f, 0, 0, 0);
}

// round 5
// speedup vs baseline: 2.7506x; 1.2502x over previous
#include <cuda_runtime.h>
#include <cuda_fp16.h>
#include <math.h>
#include <stdint.h>

// ---------------------------------------------------------------------------
// Problem constants
// ---------------------------------------------------------------------------
#define DD 1024
#define SS 2048
#define BB 2
#define MT (BB * SS)          // 4096

// ---------------------------------------------------------------------------
// Scratch (device globals; no allocation allowed)
// ---------------------------------------------------------------------------
__device__ __half g_xh[MT * DD], g_xl[MT * DD];
__device__ __half g_wt16[DD * DD];                    // wi^T fp16
__device__ float  g_w2[DD * DD];
__device__ __half g_w2t16[DD * DD];                   // W2^T fp16
__device__ float  g_q[MT * DD];
__device__ __half g_qh[MT * DD], g_ql[MT * DD];
__device__ __half g_qt16[MT * DD];                    // q^T per batch, fp16
__device__ float  g_sc[(size_t)BB * SS * SS];
__device__ __half g_ph[(size_t)BB * SS * SS], g_pl[(size_t)BB * SS * SS];
__device__ __half g_heh[MT * DD], g_hel[MT * DD];     // head hi/lo
__device__ float  g_hn[MT * DD];                      // h (pre-LN)
__device__ __half g_nh[MT * DD], g_nl[MT * DD];       // LN(h) hi/lo
__device__ __half g_th[MT * DD], g_tl[MT * DD];       // swish out hi/lo

// ---------------------------------------------------------------------------
// PTX helpers (baseline ISA only)
// ---------------------------------------------------------------------------
__device__ __forceinline__ uint32_t smem_to_u32(const void* p) {
    uint32_t a;
    asm("{ .reg .u64 t; cvta.to.shared.u64 t, %1; cvt.u32.u64 %0, t; }"
        : "=r"(a) : "l"(p));
    return a;
}
__device__ __forceinline__ void cpasync16(uint32_t dst, const void* src) {
    asm volatile("cp.async.cg.shared.global [%0], [%1], 16;" :: "r"(dst), "l"(src));
}
#define CP_COMMIT() asm volatile("cp.async.commit_group;" ::: "memory")
#define CP_WAIT(n)  asm volatile("cp.async.wait_group %0;" :: "n"(n) : "memory")

__device__ __forceinline__ void ldsm4(uint32_t* r, uint32_t addr) {
    asm volatile("ldmatrix.sync.aligned.m8n8.x4.shared.b16 {%0,%1,%2,%3}, [%4];"
                 : "=r"(r[0]), "=r"(r[1]), "=r"(r[2]), "=r"(r[3]) : "r"(addr));
}
__device__ __forceinline__ void mma16816(float* c, const uint32_t* a, const uint32_t* b) {
    asm volatile(
        "mma.sync.aligned.m16n8k16.row.col.f32.f16.f16.f32 "
        "{%0,%1,%2,%3}, {%4,%5,%6,%7}, {%8,%9}, {%0,%1,%2,%3};"
        : "+f"(c[0]), "+f"(c[1]), "+f"(c[2]), "+f"(c[3])
        : "r"(a[0]), "r"(a[1]), "r"(a[2]), "r"(a[3]), "r"(b[0]), "r"(b[1]));
}

// ---------------------------------------------------------------------------
// fp32 -> fp16 hi/lo split
// ---------------------------------------------------------------------------
__device__ __forceinline__ void split1(float v, __half& h, __half& l) {
    h = __float2half(v);
    l = __float2half(v - __half2float(h));
}

// ---------------------------------------------------------------------------
// Elementwise / reshape kernels
// ---------------------------------------------------------------------------
__global__ void split_kernel(const float* __restrict__ in,
                             __half* __restrict__ oh,
                             __half* __restrict__ ol, int n4) {
    int i = blockIdx.x * blockDim.x + threadIdx.x;
    if (i >= n4) return;
    float4 v = ((const float4*)in)[i];
    __half h, l;
    size_t b = (size_t)i * 4;
    split1(v.x, h, l); oh[b + 0] = h; ol[b + 0] = l;
    split1(v.y, h, l); oh[b + 1] = h; ol[b + 1] = l;
    split1(v.z, h, l); oh[b + 2] = h; ol[b + 2] = l;
    split1(v.w, h, l); oh[b + 3] = h; ol[b + 3] = l;
}

// out[c][r] = fp16(in[r][c]); out dims [C,R]; z-batched
__global__ void transpose_h_kernel(const float* __restrict__ in,
                                   __half* __restrict__ o16,
                                   int R, int C, long sin, long sout) {
    __shared__ float t[32][33];
    in += (size_t)blockIdx.z * sin;
    o16 += (size_t)blockIdx.z * sout;
    int r0 = blockIdx.y * 32, c0 = blockIdx.x * 32;
    for (int i = threadIdx.y; i < 32; i += 8)
        t[i][threadIdx.x] = in[(size_t)(r0 + i) * C + c0 + threadIdx.x];
    __syncthreads();
    for (int i = threadIdx.y; i < 32; i += 8) {
        size_t o = (size_t)(c0 + i) * R + r0 + threadIdx.x;
        o16[o] = __float2half(t[threadIdx.x][i]);
    }
}

__global__ void w2_reduce_kernel(const float* __restrict__ ok,
                                 float* __restrict__ w2, int H) {
    int idx = blockIdx.x * blockDim.x + threadIdx.x;
    if (idx >= DD * DD) return;
    int i = idx / DD, j = idx % DD;
    float s = 0.f;
    for (int h = 0; h < H; h++) s += ok[(size_t)(h * DD + i) * DD + j];
    w2[idx] = s;
}

// Causal softmax. One block per (batch,row). Reads only cols [0, L); writes P
// hi/lo for cols [0, Kc), Kc = ceil128(L); zeros beyond L. P@V clamps K to Kc.
__global__ void softmax_kernel(const float* __restrict__ S,
                               __half* __restrict__ ph,
                               __half* __restrict__ pl) {
    __shared__ float red[256];
    const int tid = threadIdx.x;
    const int L = (blockIdx.x & (SS - 1)) + 1;
    const int Kc = (L + 127) & ~127;
    const size_t base = (size_t)blockIdx.x * SS;

    float vals[8];
    float m = -3.0e38f;
    int n = 0;
    for (int c = tid; c < L; c += 256) {
        float v = S[base + c];
        vals[n++] = v;
        m = fmaxf(m, v);
    }
    red[tid] = m; __syncthreads();
    for (int s = 128; s > 0; s >>= 1) { if (tid < s) red[tid] = fmaxf(red[tid], red[tid + s]); __syncthreads(); }
    m = red[0]; __syncthreads();

    float sum = 0.f;
#pragma unroll 8
    for (int i = 0; i < n; i++) { vals[i] = expf(vals[i] - m); sum += vals[i]; }
    red[tid] = sum; __syncthreads();
    for (int s = 128; s > 0; s >>= 1) { if (tid < s) red[tid] += red[tid + s]; __syncthreads(); }
    float inv = 1.0f / red[0];

    n = 0;
    for (int c = tid; c < Kc; c += 256) {
        float p = (c < L) ? vals[n] * inv : 0.f;
        if (c < L) n++;
        __half h, l;
        split1(p, h, l);
        ph[base + c] = h; pl[base + c] = l;
    }
}

__global__ void layernorm_kernel(const float* __restrict__ H,
                                 __half* __restrict__ oh,
                                 __half* __restrict__ ol) {
    __shared__ float red[256];
    int tid = threadIdx.x;
    size_t base = (size_t)blockIdx.x * DD;
    float4 v = ((const float4*)(H + base))[tid];

    red[tid] = v.x + v.y + v.z + v.w; __syncthreads();
    for (int s = 128; s > 0; s >>= 1) { if (tid < s) red[tid] += red[tid + s]; __syncthreads(); }
    float mean = red[0] * (1.0f / DD); __syncthreads();
    red[tid] = v.x * v.x + v.y * v.y + v.z * v.z + v.w * v.w; __syncthreads();
    for (int s = 128; s > 0; s >>= 1) { if (tid < s) red[tid] += red[tid + s]; __syncthreads(); }
    float msq = red[0] * (1.0f / DD);
    float inv = 1.0f / sqrtf(msq - mean * mean + 1e-5f);

    __half h, l;
    size_t o = base + (size_t)tid * 4;
    split1((v.x - mean) * inv, h, l); oh[o + 0] = h; ol[o + 0] = l;
    split1((v.y - mean) * inv, h, l); oh[o + 1] = h; ol[o + 1] = l;
    split1((v.z - mean) * inv, h, l); oh[o + 2] = h; ol[o + 2] = l;
    split1((v.w - mean) * inv, h, l); oh[o + 3] = h; ol[o + 3] = l;
}

// ---------------------------------------------------------------------------
// HMMA fp16 split GEMM: C[z] = A[z] @ B[z]^T  (A:[M,K] hi/lo, B:[N,K])
// BSPLIT=false: B single fp16, 2 products (ah*b + al*b)      — err ~2^-12
// BSPLIT=true : B hi/lo fp16, 3 products (hh + hl + lh)      — err ~2^-22
// 128x128 block tile, BK=32, 8 warps (4M x 2N), warp tile 32x64.
// 3-stage cp.async pipeline; accumulator-reuse-distance-maximized MMA order.
// ---------------------------------------------------------------------------
enum { EPI_F32 = 0, EPI_QOUT = 1, EPI_SCORES = 2, EPI_RESID = 3, EPI_BIAS = 4, EPI_SWISH = 5 };

#define LDS_T 40                        // smem row stride (halves): conflict-free ldmatrix
#define TEN_B (128 * LDS_T * 2)         // one tensor tile: 10240 B
#define BUF_B (4 * TEN_B)               // slots: Ah, Al, Bh, [Bl]
#define STAGES 3
#define SMEM_BYTES (STAGES * BUF_B)     // 122880 B

__device__ __forceinline__ void load_tensor(uint32_t sdst, const __half* g,
                                            int base_row, int ldK, int kofs, int tid) {
#pragma unroll
    for (int i = 0; i < 2; i++) {
        int v = tid * 2 + i;                 // 0..511
        int row = v >> 2, cseg = v & 3;
        uint32_t dst = sdst + (uint32_t)(row * LDS_T + cseg * 8) * 2;
        cpasync16(dst, g + (size_t)(base_row + row) * ldK + kofs + cseg * 8);
    }
}

template <int EPI, bool CAUSAL, bool KCLAMP, bool BSPLIT>
__global__ __launch_bounds__(256, 1) void gemm_tc(
    int M, int N, int K,
    const __half* __restrict__ Ah, const __half* __restrict__ Al,
    const __half* __restrict__ Bh, const __half* __restrict__ Bl,
    float* __restrict__ Cf,
    __half* __restrict__ Ch, __half* __restrict__ Cl,
    const float* __restrict__ Ef, float scale,
    long sA, long sB, long sC) {
    extern __shared__ char smem[];
    const int tid = threadIdx.x;
    const int rowStart = blockIdx.y * 128, colStart = blockIdx.x * 128;
    const int z = blockIdx.z;

    // Fully masked score tile: nothing to do (softmax never reads it).
    if (CAUSAL && colStart > rowStart) return;

    Ah += (size_t)z * sA; Al += (size_t)z * sA;
    Bh += (size_t)z * sB;
    if (BSPLIT) Bl += (size_t)z * sB;
    const size_t cofs = (size_t)z * sC;

    const uint32_t sb = smem_to_u32(smem);
    const int lane = tid & 31, wid = tid >> 5;
    const int warp_m = wid & 3, warp_n = wid >> 2;

    const int NC = (KCLAMP ? (rowStart + 128) : K) / 32;

    const int a_row = warp_m * 32 + (lane & 15);
    const int a_col = (lane >> 4) * 8;
    const int b_row = warp_n * 64 + (lane & 7) + ((lane >> 4) & 1) * 8;
    const int b_col = ((lane >> 3) & 1) * 8;

    float acc[2][8][4];
#pragma unroll
    for (int i = 0; i < 2; i++)
#pragma unroll
        for (int j = 0; j < 8; j++)
#pragma unroll
            for (int q = 0; q < 4; q++) acc[i][j][q] = 0.f;

    // prologue: stages 0, 1
    {
        load_tensor(sb + 0 * TEN_B, Ah, rowStart, K, 0, tid);
        load_tensor(sb + 1 * TEN_B, Al, rowStart, K, 0, tid);
        load_tensor(sb + 2 * TEN_B, Bh, colStart, K, 0, tid);
        if (BSPLIT) load_tensor(sb + 3 * TEN_B, Bl, colStart, K, 0, tid);
        CP_COMMIT();
        if (NC > 1) {
            load_tensor(sb + BUF_B + 0 * TEN_B, Ah, rowStart, K, 32, tid);
            load_tensor(sb + BUF_B + 1 * TEN_B, Al, rowStart, K, 32, tid);
            load_tensor(sb + BUF_B + 2 * TEN_B, Bh, colStart, K, 32, tid);
            if (BSPLIT) load_tensor(sb + BUF_B + 3 * TEN_B, Bl, colStart, K, 32, tid);
            CP_COMMIT();
        }
    }

    int bufIdx = 0;
    for (int c = 0; c < NC; c++) {
        if (c + 1 < NC) { CP_WAIT(1); } else { CP_WAIT(0); }
        __syncthreads();

        if (c + 2 < NC) {
            int nIdx = bufIdx + 2; if (nIdx >= STAGES) nIdx -= STAGES;
            const uint32_t nbuf = sb + (uint32_t)nIdx * BUF_B;
            const int kofs = (c + 2) * 32;
            load_tensor(nbuf + 0 * TEN_B, Ah, rowStart, K, kofs, tid);
            load_tensor(nbuf + 1 * TEN_B, Al, rowStart, K, kofs, tid);
            load_tensor(nbuf + 2 * TEN_B, Bh, colStart, K, kofs, tid);
            if (BSPLIT) load_tensor(nbuf + 3 * TEN_B, Bl, colStart, K, kofs, tid);
            CP_COMMIT();
        }

        const uint32_t buf = sb + (uint32_t)bufIdx * BUF_B;
#pragma unroll
        for (int k0 = 0; k0 < 32; k0 += 16) {
            uint32_t ah[2][4], al[2][4], bh[4][4], bl[4][4];
#pragma unroll
            for (int mt = 0; mt < 2; mt++) {
                uint32_t ao = (uint32_t)((a_row + mt * 16) * LDS_T + k0 + a_col) * 2;
                ldsm4(ah[mt], buf + 0 * TEN_B + ao);
                ldsm4(al[mt], buf + 1 * TEN_B + ao);
            }
#pragma unroll
            for (int np = 0; np < 4; np++) {
                uint32_t bo = (uint32_t)((b_row + np * 16) * LDS_T + k0 + b_col) * 2;
                ldsm4(bh[np], buf + 2 * TEN_B + bo);
                if (BSPLIT) ldsm4(bl[np], buf + 3 * TEN_B + bo);
            }
            // pass 1: ah * bh
#pragma unroll
            for (int mt = 0; mt < 2; mt++)
#pragma unroll
                for (int np = 0; np < 4; np++) {
                    mma16816(acc[mt][2 * np + 0], ah[mt], &bh[np][0]);
                    mma16816(acc[mt][2 * np + 1], ah[mt], &bh[np][2]);
                }
            // pass 2: al * bh
#pragma unroll
            for (int mt = 0; mt < 2; mt++)
#pragma unroll
                for (int np = 0; np < 4; np++) {
                    mma16816(acc[mt][2 * np + 0], al[mt], &bh[np][0]);
                    mma16816(acc[mt][2 * np + 1], al[mt], &bh[np][2]);
                }
            // pass 3 (BSPLIT only): ah * bl
            if (BSPLIT) {
#pragma unroll
                for (int mt = 0; mt < 2; mt++)
#pragma unroll
                    for (int np = 0; np < 4; np++) {
                        mma16816(acc[mt][2 * np + 0], ah[mt], &bl[np][0]);
                        mma16816(acc[mt][2 * np + 1], ah[mt], &bl[np][2]);
                    }
            }
        }
        bufIdx++; if (bufIdx >= STAGES) bufIdx = 0;
    }

    // epilogue: registers -> gmem
#pragma unroll
    for (int mt = 0; mt < 2; mt++)
#pragma unroll
        for (int nt = 0; nt < 8; nt++) {
            const float* a = acc[mt][nt];
            int r0 = rowStart + warp_m * 32 + mt * 16 + (lane >> 2);
            int c0 = colStart + warp_n * 64 + nt * 8 + (lane & 3) * 2;
#pragma unroll
            for (int half = 0; half < 2; half++) {
                int gr = r0 + half * 8;
                float x0 = a[half * 2 + 0], x1 = a[half * 2 + 1];
                size_t o = cofs + (size_t)gr * N + c0;
                if (EPI == EPI_F32) {
                    *(float2*)(Cf + o) = make_float2(x0, x1);
                } else if (EPI == EPI_QOUT) {
                    *(float2*)(Cf + o) = make_float2(x0, x1);
                    __half h0, l0, h1, l1;
                    split1(x0, h0, l0); split1(x1, h1, l1);
                    *(__half2*)(Ch + o) = __halves2half2(h0, h1);
                    *(__half2*)(Cl + o) = __halves2half2(l0, l1);
                } else if (EPI == EPI_SCORES) {
                    // masked entries (col > row) may be garbage; never read.
                    *(float2*)(Cf + o) = make_float2(x0 * scale, x1 * scale);
                } else if (EPI == EPI_RESID) {
                    float2 e = *(const float2*)(Ef + o);
                    x0 += e.x; x1 += e.y;
                    __half h0, l0, h1, l1;
                    split1(x0, h0, l0); split1(x1, h1, l1);
                    *(__half2*)(Ch + o) = __halves2half2(h0, h1);
                    *(__half2*)(Cl + o) = __halves2half2(l0, l1);
                } else if (EPI == EPI_BIAS) {
                    x0 += Ef[c0]; x1 += Ef[c0 + 1];
                    *(float2*)(Cf + o) = make_float2(x0, x1);
                } else if (EPI == EPI_SWISH) {
                    x0 = x0 / (1.f + expf(-x0));
                    x1 = x1 / (1.f + expf(-x1));
                    __half h0, l0, h1, l1;
                    split1(x0, h0, l0); split1(x1, h1, l1);
                    *(__half2*)(Ch + o) = __halves2half2(h0, h1);
                    *(__half2*)(Cl + o) = __halves2half2(l0, l1);
                }
            }
        }
}

// ---------------------------------------------------------------------------
extern "C" void kernel_launch(void* const* d_in, const int* in_sizes, int n_in,
                              void* d_out, int out_size) {
    const float* x    = (const float*)d_in[0];
    const float* wi   = (const float*)d_in[2];
    const float* ok   = (const float*)d_in[3];
    const float* bias = (const float*)d_in[4];
    float* out = (float*)d_out;
    int H = in_sizes[3] / (DD * DD);

    float *q, *w2, *sc, *hn;
    __half *xh, *xl, *wt16, *w2t16, *qh, *ql, *qt16;
    __half *pph, *ppl, *heh, *hel, *nh, *nl, *th, *tl;
    cudaGetSymbolAddress((void**)&q,     g_q);
    cudaGetSymbolAddress((void**)&w2,    g_w2);
    cudaGetSymbolAddress((void**)&sc,    g_sc);
    cudaGetSymbolAddress((void**)&hn,    g_hn);
    cudaGetSymbolAddress((void**)&xh,    g_xh);    cudaGetSymbolAddress((void**)&xl,   g_xl);
    cudaGetSymbolAddress((void**)&wt16,  g_wt16);
    cudaGetSymbolAddress((void**)&w2t16, g_w2t16);
    cudaGetSymbolAddress((void**)&qh,    g_qh);    cudaGetSymbolAddress((void**)&ql,   g_ql);
    cudaGetSymbolAddress((void**)&qt16,  g_qt16);
    cudaGetSymbolAddress((void**)&pph,   g_ph);    cudaGetSymbolAddress((void**)&ppl,  g_pl);
    cudaGetSymbolAddress((void**)&heh,   g_heh);   cudaGetSymbolAddress((void**)&hel,  g_hel);
    cudaGetSymbolAddress((void**)&nh,    g_nh);    cudaGetSymbolAddress((void**)&nl,   g_nl);
    cudaGetSymbolAddress((void**)&th,    g_th);    cudaGetSymbolAddress((void**)&tl,   g_tl);

    cudaFuncSetAttribute((const void*)gemm_tc<EPI_QOUT,   false, false, false>, cudaFuncAttributeMaxDynamicSharedMemorySize, SMEM_BYTES);
    cudaFuncSetAttribute((const void*)gemm_tc<EPI_SCORES, true,  false, true >, cudaFuncAttributeMaxDynamicSharedMemorySize, SMEM_BYTES);
    cudaFuncSetAttribute((const void*)gemm_tc<EPI_RESID,  false, true,  false>, cudaFuncAttributeMaxDynamicSharedMemorySize, SMEM_BYTES);
    cudaFuncSetAttribute((const void*)gemm_tc<EPI_BIAS,   false, false, false>, cudaFuncAttributeMaxDynamicSharedMemorySize, SMEM_BYTES);
    cudaFuncSetAttribute((const void*)gemm_tc<EPI_SWISH,  false, false, false>, cudaFuncAttributeMaxDynamicSharedMemorySize, SMEM_BYTES);
    cudaFuncSetAttribute((const void*)gemm_tc<EPI_F32,    false, false, false>, cudaFuncAttributeMaxDynamicSharedMemorySize, SMEM_BYTES);

    // --- preprocessing ---
    split_kernel<<<(MT * DD / 4 + 255) / 256, 256>>>(x, xh, xl, MT * DD / 4);
    transpose_h_kernel<<<dim3(32, 32, 1), dim3(32, 8)>>>(wi, wt16, DD, DD, 0, 0);
    w2_reduce_kernel<<<(DD * DD + 255) / 256, 256>>>(ok, w2, H);
    transpose_h_kernel<<<dim3(32, 32, 1), dim3(32, 8)>>>(w2, w2t16, DD, DD, 0, 0);

    // q = x @ wi  (A split, B = wi^T fp16)  -> q fp32 + hi/lo
    gemm_tc<EPI_QOUT, false, false, false><<<dim3(DD / 128, MT / 128, 1), 256, SMEM_BYTES>>>(
        MT, DD, DD, xh, xl, wt16, nullptr, q, qh, ql, nullptr, 0.f, 0, 0, 0);

    // q^T per batch (single fp16, B operand for P@V)
    transpose_h_kernel<<<dim3(32, 64, BB), dim3(32, 8)>>>(
        q, qt16, SS, DD, (long)SS * DD, (long)SS * DD);

    // scores = (q @ q^T)/32  — both operands split (3 products), tri-skip
    gemm_tc<EPI_SCORES, true, false, true><<<dim3(SS / 128, SS / 128, BB), 256, SMEM_BYTES>>>(
        SS, SS, DD, qh, ql, qh, ql, sc, nullptr, nullptr, nullptr, 1.0f / 32.0f,
        (long)SS * DD, (long)SS * DD, (long)SS * SS);

    // causal softmax -> P hi/lo (zeros to 128-padded boundary)
    softmax_kernel<<<BB * SS, 256>>>(sc, pph, ppl);

    // head = q + P @ q   (A = P split, B = q^T fp16, causal K clamp)
    gemm_tc<EPI_RESID, false, true, false><<<dim3(DD / 128, SS / 128, BB), 256, SMEM_BYTES>>>(
        SS, DD, SS, pph, ppl, qt16, nullptr, nullptr, heh, hel, q, 0.f,
        (long)SS * SS, (long)SS * DD, (long)SS * DD);

    // h = head @ W2 + bias -> fp32
    gemm_tc<EPI_BIAS, false, false, false><<<dim3(DD / 128, MT / 128, 1), 256, SMEM_BYTES>>>(
        MT, DD, DD, heh, hel, w2t16, nullptr, hn, nullptr, nullptr, bias, 0.f, 0, 0, 0);

    // LayerNorm -> hi/lo
    layernorm_kernel<<<MT, 256>>>(hn, nh, nl);

    // t = swish(h @ wi) -> hi/lo
    gemm_tc<EPI_SWISH, false, false, false><<<dim3(DD / 128, MT / 128, 1), 256, SMEM_BYTES>>>(
        MT, DD, DD, nh, nl, wt16, nullptr, nullptr, th, tl, nullptr, 0.f, 0, 0, 0);

    // out = t @ wi -> fp32
    gemm_tc<EPI_F32, false, false, false><<<dim3(DD / 128, MT / 128, 1), 256, SMEM_BYTES>>>(
        MT, DD, DD, th, tl, wt16, nullptr, out, nullptr, nullptr, nullptr, 0.f, 0, 0, 0);
}